// round 12
// baseline (speedup 1.0000x reference)
#include <cuda_runtime.h>
#include <math.h>
#include <stdint.h>

// Problem constants
#define Nn   256
#define Ll   384
#define Dd   256
#define DP   128
#define Hh   8
#define DHh  32
#define NL   (Nn*Ll)      // 98304 rows
#define LLp  (Ll*Ll)      // 147456
#define EPSF 1e-5f
#define SCALE 0.17677669529663687f  // 1/sqrt(32)

// ---------------- scratch (device globals; no allocation allowed) ----------------
__device__ uint32_t g_mt [NL*Dd];   // LN(msa) in tf32
__device__ uint32_t g_qt [NL*Dd];   // q * seq_weight, tf32
__device__ uint32_t g_kt [NL*Dd];   // k * scale, tf32
__device__ uint32_t g_vt [NL*Dd];   // v, tf32
__device__ float    g_g  [NL*Dd];   // gate (fp32)
__device__ uint32_t g_ot [NL*Dd];   // (attn@v)*gate, tf32
__device__ float    g_qsw[Ll*Dd];   // seq-weight queries (fp32)
__device__ float    g_sw [NL*Hh];   // sw logits -> seq weights
__device__ float    g_logits[Hh*LLp]; // logits(+bias) fp32 -> attn tf32 (in place)
__device__ float    g_bias  [Hh*LLp]; // pair bias
__device__ uint32_t g_wt [7*Dd*Dd];  // tf32 weights: Wq_sw,Wk_sw,Wq,Wk,Wv,Wg,Wo

// ---------------- helpers ----------------
__device__ __forceinline__ uint32_t f2tf32(float f) {
    uint32_t r;
    asm("cvt.rna.tf32.f32 %0, %1;" : "=r"(r) : "f"(f));
    return r;
}

__device__ __forceinline__ void mma_tf32(float& c0, float& c1, float& c2, float& c3,
                                         uint32_t a0, uint32_t a1, uint32_t a2, uint32_t a3,
                                         uint32_t b0, uint32_t b1) {
    asm volatile("mma.sync.aligned.m16n8k8.row.col.f32.tf32.tf32.f32 "
                 "{%0,%1,%2,%3}, {%4,%5,%6,%7}, {%8,%9}, {%0,%1,%2,%3};"
                 : "+f"(c0), "+f"(c1), "+f"(c2), "+f"(c3)
                 : "r"(a0), "r"(a1), "r"(a2), "r"(a3), "r"(b0), "r"(b1));
}

__device__ __forceinline__ void cpa16(uint32_t smem, const void* gmem) {
    asm volatile("cp.async.cg.shared.global [%0], [%1], 16;" :: "r"(smem), "l"(gmem));
}
#define CP_COMMIT() asm volatile("cp.async.commit_group;")
#define CP_WAIT1()  asm volatile("cp.async.wait_group 1;")
#define CP_WAIT0()  asm volatile("cp.async.wait_group 0;")

// ---------------- LayerNorm msa -> tf32 (one row per block) ----------------
__global__ void ln_tf32_kernel(const float* __restrict__ x, const float* __restrict__ g,
                               const float* __restrict__ b, uint32_t* __restrict__ out) {
    __shared__ float s1[8], s2[8];
    __shared__ float mu_s, rs_s;
    int row = blockIdx.x;
    int t = threadIdx.x;
    float v = x[(size_t)row*Dd + t];
    float s = v, q = v*v;
    #pragma unroll
    for (int o = 16; o; o >>= 1) {
        s += __shfl_down_sync(0xffffffffu, s, o);
        q += __shfl_down_sync(0xffffffffu, q, o);
    }
    int lane = t & 31, w = t >> 5;
    if (!lane) { s1[w] = s; s2[w] = q; }
    __syncthreads();
    if (w == 0) {
        float ss = (lane < 8) ? s1[lane] : 0.f;
        float qq = (lane < 8) ? s2[lane] : 0.f;
        #pragma unroll
        for (int o = 16; o; o >>= 1) {
            ss += __shfl_down_sync(0xffffffffu, ss, o);
            qq += __shfl_down_sync(0xffffffffu, qq, o);
        }
        if (!lane) {
            float mu = ss * (1.0f/Dd);
            float var = qq * (1.0f/Dd) - mu*mu;
            mu_s = mu;
            rs_s = rsqrtf(var + EPSF);
        }
    }
    __syncthreads();
    out[(size_t)row*Dd + t] = f2tf32((v - mu_s) * rs_s * g[t] + b[t]);
}

// ---------------- weight fp32 -> tf32 ----------------
__global__ void wconv_kernel(const float* __restrict__ src, uint32_t* __restrict__ dst) {
    int i = blockIdx.x*256 + threadIdx.x;
    dst[i] = f2tf32(src[i]);
}

// ============================================================================
// Pure TF32 GEMM, cp.async double-buffered. C[Mx256] = A[tf32] @ B[tf32].
// BM=128, BN=128, BK=32, 256 threads (8 warps 4x2), 2 CTAs/SM.
// Epilogue flags: BIAS(+bias), SIG(sigmoid), SWL(sw_logits dot, no C store),
// SWMUL(*swp[row][col>>5]), TF32OUT(store tf32 to Ct else fp32 to Cf).
// ============================================================================
#define GP_ASZ (128*36)
#define GP_BSZ (32*136)
#define GP_SMEM ((2*GP_ASZ + 2*GP_BSZ)*4)

template<bool BIAS, bool SIG, bool SWL, bool SWMUL, bool TF32OUT>
__global__ void __launch_bounds__(256,2) gemmP(
        const uint32_t* __restrict__ A, const uint32_t* __restrict__ B,
        const float* __restrict__ bias, const float* __restrict__ qsw,
        float* __restrict__ swl, const float* __restrict__ swp,
        float scale, float* __restrict__ Cf, uint32_t* __restrict__ Ct) {
    extern __shared__ uint32_t sh[];
    uint32_t* Asm = sh;
    uint32_t* Bsm = sh + 2*GP_ASZ;
    uint32_t sA0 = (uint32_t)__cvta_generic_to_shared(Asm);
    uint32_t sB0 = (uint32_t)__cvta_generic_to_shared(Bsm);
    int tid = threadIdx.x;
    int wid = tid >> 5, lane = tid & 31;
    int gid = lane >> 2, tig = lane & 3;
    int wm0 = (wid >> 1) * 32;
    int wn0 = (wid & 1) * 64;
    int m0 = blockIdx.y * 128, n0 = blockIdx.x * 128;

    int ar[4], ac[4], br[4], bc[4];
    #pragma unroll
    for (int u = 0; u < 4; u++) {
        int f = tid + u*256;
        ar[u] = f >> 3; ac[u] = (f & 7) * 4;
        br[u] = f >> 5; bc[u] = (f & 31) * 4;
    }
    auto prefetch = [&](int kt, int buf) {
        #pragma unroll
        for (int u = 0; u < 4; u++) {
            cpa16(sA0 + (uint32_t)(buf*GP_ASZ + ar[u]*36 + ac[u])*4,
                  A + (size_t)(m0+ar[u])*Dd + kt*32 + ac[u]);
            cpa16(sB0 + (uint32_t)(buf*GP_BSZ + br[u]*136 + bc[u])*4,
                  B + (size_t)(kt*32+br[u])*Dd + n0 + bc[u]);
        }
        CP_COMMIT();
    };

    float acc[2][8][4] = {};
    prefetch(0, 0); prefetch(1, 1);
    for (int kt = 0; kt < 8; kt++) {
        if (kt < 7) CP_WAIT1(); else CP_WAIT0();
        __syncthreads();
        const uint32_t* Ab = Asm + (kt&1)*GP_ASZ;
        const uint32_t* Bb = Bsm + (kt&1)*GP_BSZ;
        #pragma unroll
        for (int kk = 0; kk < 4; kk++) {
            int kb = kk * 8;
            uint32_t a[2][4];
            #pragma unroll
            for (int mf = 0; mf < 2; mf++) {
                int r = wm0 + mf*16 + gid;
                a[mf][0] = Ab[r*36 + kb + tig];
                a[mf][1] = Ab[(r+8)*36 + kb + tig];
                a[mf][2] = Ab[r*36 + kb + tig + 4];
                a[mf][3] = Ab[(r+8)*36 + kb + tig + 4];
            }
            uint32_t b[8][2];
            #pragma unroll
            for (int nf = 0; nf < 8; nf++) {
                int cn = wn0 + nf*8 + gid;
                b[nf][0] = Bb[(kb+tig)*136 + cn];
                b[nf][1] = Bb[(kb+tig+4)*136 + cn];
            }
            #pragma unroll
            for (int mf = 0; mf < 2; mf++)
                #pragma unroll
                for (int nf = 0; nf < 8; nf++)
                    mma_tf32(acc[mf][nf][0], acc[mf][nf][1], acc[mf][nf][2], acc[mf][nf][3],
                             a[mf][0], a[mf][1], a[mf][2], a[mf][3],
                             b[nf][0], b[nf][1]);
        }
        __syncthreads();
        if (kt + 2 < 8) prefetch(kt+2, kt&1);
    }

    if (SWL) {
        #pragma unroll
        for (int mf = 0; mf < 2; mf++) {
            #pragma unroll
            for (int half = 0; half < 2; half++) {
                int row = m0 + wm0 + mf*16 + gid + half*8;
                int i = row % Ll;
                float p0 = 0.f, p1 = 0.f;
                #pragma unroll
                for (int nf = 0; nf < 8; nf++) {
                    int col = n0 + wn0 + nf*8 + tig*2;
                    float v0 = acc[mf][nf][half*2 + 0] + bias[col];
                    float v1 = acc[mf][nf][half*2 + 1] + bias[col+1];
                    float2 qv = *(const float2*)(qsw + (size_t)i*Dd + col);
                    float contrib = v0*qv.x + v1*qv.y;
                    if (nf < 4) p0 += contrib; else p1 += contrib;
                }
                p0 += __shfl_xor_sync(0xffffffffu, p0, 1);
                p0 += __shfl_xor_sync(0xffffffffu, p0, 2);
                p1 += __shfl_xor_sync(0xffffffffu, p1, 1);
                p1 += __shfl_xor_sync(0xffffffffu, p1, 2);
                if (tig == 0) {
                    int h0 = (n0 + wn0) >> 5;
                    swl[(size_t)row*Hh + h0]     = p0;
                    swl[(size_t)row*Hh + h0 + 1] = p1;
                }
            }
        }
    } else {
        #pragma unroll
        for (int mf = 0; mf < 2; mf++) {
            #pragma unroll
            for (int half = 0; half < 2; half++) {
                int row = m0 + wm0 + mf*16 + gid + half*8;
                #pragma unroll
                for (int nf = 0; nf < 8; nf++) {
                    int col = n0 + wn0 + nf*8 + tig*2;
                    float v0 = acc[mf][nf][half*2 + 0];
                    float v1 = acc[mf][nf][half*2 + 1];
                    if (BIAS) { v0 += bias[col]; v1 += bias[col+1]; }
                    v0 *= scale; v1 *= scale;
                    if (SIG) {
                        v0 = 1.f / (1.f + expf(-v0));
                        v1 = 1.f / (1.f + expf(-v1));
                    }
                    if (SWMUL) {
                        float swv = swp[(size_t)row*Hh + (col >> 5)];
                        v0 *= swv; v1 *= swv;
                    }
                    if (TF32OUT) {
                        uint2 o; o.x = f2tf32(v0); o.y = f2tf32(v1);
                        *(uint2*)(Ct + (size_t)row*Dd + col) = o;
                    } else {
                        float2 o; o.x = v0; o.y = v1;
                        *(float2*)(Cf + (size_t)row*Dd + col) = o;
                    }
                }
            }
        }
    }
}

// ---------------- softmax over n (256) for each (i,h) ----------------
__global__ void swsoftmax_kernel(float* __restrict__ sw) {
    __shared__ float sm[8];
    __shared__ float red;
    int ih = blockIdx.x;
    int n = threadIdx.x;
    int lane = n & 31, w = n >> 5;
    float v = sw[(size_t)n*(Ll*Hh) + ih];
    float mx = v;
    #pragma unroll
    for (int o = 16; o; o >>= 1) mx = fmaxf(mx, __shfl_down_sync(0xffffffffu, mx, o));
    if (!lane) sm[w] = mx;
    __syncthreads();
    if (w == 0) {
        float x = (lane < 8) ? sm[lane] : -3.4e38f;
        #pragma unroll
        for (int o = 16; o; o >>= 1) x = fmaxf(x, __shfl_down_sync(0xffffffffu, x, o));
        if (!lane) red = x;
    }
    __syncthreads();
    mx = red;
    float e = expf(v - mx);
    float s = e;
    #pragma unroll
    for (int o = 16; o; o >>= 1) s += __shfl_down_sync(0xffffffffu, s, o);
    __syncthreads();
    if (!lane) sm[w] = s;
    __syncthreads();
    if (w == 0) {
        float x = (lane < 8) ? sm[lane] : 0.f;
        #pragma unroll
        for (int o = 16; o; o >>= 1) x += __shfl_down_sync(0xffffffffu, x, o);
        if (!lane) red = x;
    }
    __syncthreads();
    sw[(size_t)n*(Ll*Hh) + ih] = e / red;
}

// ---------------- pair bias: LN(pair row) @ Wb -> bias[h][i][j] ----------------
__global__ void pairbias_kernel(const float* __restrict__ pair, const float* __restrict__ g,
                                const float* __restrict__ b, const float* __restrict__ Wb,
                                float* __restrict__ bias) {
    __shared__ float s1[4], s2[4];
    __shared__ float hp[4][8];
    int ij = blockIdx.x;
    int t = threadIdx.x;
    int lane = t & 31, w = t >> 5;
    float v = pair[(size_t)ij*DP + t];
    float s = v, q = v*v;
    #pragma unroll
    for (int o = 16; o; o >>= 1) {
        s += __shfl_down_sync(0xffffffffu, s, o);
        q += __shfl_down_sync(0xffffffffu, q, o);
    }
    if (!lane) { s1[w] = s; s2[w] = q; }
    __syncthreads();
    if (w == 0) {
        float ss = (lane < 4) ? s1[lane] : 0.f;
        float qq = (lane < 4) ? s2[lane] : 0.f;
        #pragma unroll
        for (int o = 16; o; o >>= 1) {
            ss += __shfl_down_sync(0xffffffffu, ss, o);
            qq += __shfl_down_sync(0xffffffffu, qq, o);
        }
        if (!lane) { s1[0] = ss; s2[0] = qq; }
    }
    __syncthreads();
    float mu = s1[0] * (1.0f/DP);
    float var = s2[0] * (1.0f/DP) - mu*mu;
    float ln = (v - mu) * rsqrtf(var + EPSF) * g[t] + b[t];
    float p[8];
    #pragma unroll
    for (int h = 0; h < 8; h++) p[h] = ln * Wb[t*Hh + h];
    #pragma unroll
    for (int h = 0; h < 8; h++)
        #pragma unroll
        for (int o = 16; o; o >>= 1) p[h] += __shfl_down_sync(0xffffffffu, p[h], o);
    if (!lane) {
        #pragma unroll
        for (int h = 0; h < 8; h++) hp[w][h] = p[h];
    }
    __syncthreads();
    if (t < 8) {
        float x = hp[0][t] + hp[1][t] + hp[2][t] + hp[3][t];
        bias[(size_t)t*LLp + ij] = x;
    }
}

// ============================================================================
// Pure TF32 logits 128x128, cp.async double-buffered over n.
// logits[h][i][j] = sum_{n,d} qt[n,i,h,d]*kt[n,j,h,d] + bias
// grid (3, 3, 8), 256 threads.
// ============================================================================
#define LG_TSZ (128*36)
#define LG_SMEM (4*LG_TSZ*4)

__global__ void __launch_bounds__(256,2) logitsP(
        const uint32_t* __restrict__ qt, const uint32_t* __restrict__ ktm,
        const float* __restrict__ bias, float* __restrict__ out) {
    extern __shared__ uint32_t sh[];
    uint32_t* Asm = sh;
    uint32_t* Bsm = sh + 2*LG_TSZ;
    uint32_t sA0 = (uint32_t)__cvta_generic_to_shared(Asm);
    uint32_t sB0 = (uint32_t)__cvta_generic_to_shared(Bsm);
    int h = blockIdx.z;
    int i0 = blockIdx.y * 128, j0 = blockIdx.x * 128;
    int tid = threadIdx.x;
    int wid = tid >> 5, lane = tid & 31;
    int gid = lane >> 2, tig = lane & 3;
    int wm0 = (wid >> 1) * 32;
    int wn0 = (wid & 1) * 64;

    int lr[4], lc[4];
    #pragma unroll
    for (int u = 0; u < 4; u++) {
        int f = tid + u*256;
        lr[u] = f >> 3; lc[u] = (f & 7) * 4;
    }
    auto prefetch = [&](int n, int buf) {
        #pragma unroll
        for (int u = 0; u < 4; u++) {
            cpa16(sA0 + (uint32_t)(buf*LG_TSZ + lr[u]*36 + lc[u])*4,
                  qt + (size_t)(n*Ll + i0 + lr[u])*Dd + h*DHh + lc[u]);
            cpa16(sB0 + (uint32_t)(buf*LG_TSZ + lr[u]*36 + lc[u])*4,
                  ktm + (size_t)(n*Ll + j0 + lr[u])*Dd + h*DHh + lc[u]);
        }
        CP_COMMIT();
    };

    float acc[2][8][4] = {};
    prefetch(0, 0); prefetch(1, 1);
    for (int n = 0; n < Nn; n++) {
        if (n < Nn-1) CP_WAIT1(); else CP_WAIT0();
        __syncthreads();
        const uint32_t* Ab = Asm + (n&1)*LG_TSZ;
        const uint32_t* Bb = Bsm + (n&1)*LG_TSZ;
        #pragma unroll
        for (int kk = 0; kk < 4; kk++) {
            int kb = kk * 8;
            uint32_t a[2][4];
            #pragma unroll
            for (int mf = 0; mf < 2; mf++) {
                int r = wm0 + mf*16 + gid;
                a[mf][0] = Ab[r*36 + kb + tig];
                a[mf][1] = Ab[(r+8)*36 + kb + tig];
                a[mf][2] = Ab[r*36 + kb + tig + 4];
                a[mf][3] = Ab[(r+8)*36 + kb + tig + 4];
            }
            uint32_t b[8][2];
            #pragma unroll
            for (int nf = 0; nf < 8; nf++) {
                int cn = wn0 + nf*8 + gid;
                b[nf][0] = Bb[cn*36 + kb + tig];
                b[nf][1] = Bb[cn*36 + kb + tig + 4];
            }
            #pragma unroll
            for (int mf = 0; mf < 2; mf++)
                #pragma unroll
                for (int nf = 0; nf < 8; nf++)
                    mma_tf32(acc[mf][nf][0], acc[mf][nf][1], acc[mf][nf][2], acc[mf][nf][3],
                             a[mf][0], a[mf][1], a[mf][2], a[mf][3],
                             b[nf][0], b[nf][1]);
        }
        __syncthreads();
        if (n + 2 < Nn) prefetch(n+2, n&1);
    }
    #pragma unroll
    for (int mf = 0; mf < 2; mf++) {
        #pragma unroll
        for (int half = 0; half < 2; half++) {
            int i = i0 + wm0 + mf*16 + gid + half*8;
            #pragma unroll
            for (int nf = 0; nf < 8; nf++) {
                int j = j0 + wn0 + nf*8 + tig*2;
                size_t idx = (size_t)h*LLp + (size_t)i*Ll + j;
                float2 bb = *(const float2*)(bias + idx);
                float2 o;
                o.x = acc[mf][nf][half*2 + 0] + bb.x;
                o.y = acc[mf][nf][half*2 + 1] + bb.y;
                *(float2*)(out + idx) = o;
            }
        }
    }
}

// ---------------- softmax over j (384), writes tf32 for attn@v ----------------
__global__ void attnsoftmax_kernel(float* __restrict__ logits) {
    __shared__ float sm[12];
    __shared__ float red;
    int hi = blockIdx.x;
    size_t base = (size_t)hi * Ll;
    int j = threadIdx.x;
    int lane = j & 31, w = j >> 5;
    float v = logits[base + j];
    float mx = v;
    #pragma unroll
    for (int o = 16; o; o >>= 1) mx = fmaxf(mx, __shfl_down_sync(0xffffffffu, mx, o));
    if (!lane) sm[w] = mx;
    __syncthreads();
    if (w == 0) {
        float x = (lane < 12) ? sm[lane] : -3.4e38f;
        #pragma unroll
        for (int o = 16; o; o >>= 1) x = fmaxf(x, __shfl_down_sync(0xffffffffu, x, o));
        if (!lane) red = x;
    }
    __syncthreads();
    mx = red;
    float e = expf(v - mx);
    float s = e;
    #pragma unroll
    for (int o = 16; o; o >>= 1) s += __shfl_down_sync(0xffffffffu, s, o);
    __syncthreads();
    if (!lane) sm[w] = s;
    __syncthreads();
    if (w == 0) {
        float x = (lane < 12) ? sm[lane] : 0.f;
        #pragma unroll
        for (int o = 16; o; o >>= 1) x += __shfl_down_sync(0xffffffffu, x, o);
        if (!lane) red = x;
    }
    __syncthreads();
    ((uint32_t*)logits)[base + j] = f2tf32(e / red);
}

// ============================================================================
// Pure TF32 attn@V 128x128, cp.async double-buffered, fused gate.
// out = (attn @ v) * gate, stored tf32. grid (64, 3, 8).
// ============================================================================
__global__ void __launch_bounds__(256,2) outP(
        const uint32_t* __restrict__ attn, const uint32_t* __restrict__ vt,
        const float* __restrict__ gate, uint32_t* __restrict__ o) {
    extern __shared__ uint32_t sh[];
    uint32_t* Asm = sh;
    uint32_t* Bsm = sh + 2*GP_ASZ;
    uint32_t sA0 = (uint32_t)__cvta_generic_to_shared(Asm);
    uint32_t sB0 = (uint32_t)__cvta_generic_to_shared(Bsm);
    int h = blockIdx.z;
    int i0 = blockIdx.y * 128, c0 = blockIdx.x * 128;
    int tid = threadIdx.x;
    int wid = tid >> 5, lane = tid & 31;
    int gid = lane >> 2, tig = lane & 3;
    int wm0 = (wid >> 1) * 32;
    int wn0 = (wid & 1) * 64;

    int ar[4], ac[4], brr[4], bsg[4], bnn[4], bdd[4];
    #pragma unroll
    for (int u = 0; u < 4; u++) {
        int f = tid + u*256;
        ar[u] = f >> 3; ac[u] = (f & 7) * 4;
        brr[u] = f >> 5;
        int seg = f & 31;
        bsg[u] = seg * 4;
        int cg = c0 + seg*4;
        bnn[u] = cg >> 5; bdd[u] = cg & 31;
    }
    auto prefetch = [&](int jt, int buf) {
        int j0 = jt * 32;
        #pragma unroll
        for (int u = 0; u < 4; u++) {
            cpa16(sA0 + (uint32_t)(buf*GP_ASZ + ar[u]*36 + ac[u])*4,
                  attn + (size_t)h*LLp + (size_t)(i0 + ar[u])*Ll + j0 + ac[u]);
            cpa16(sB0 + (uint32_t)(buf*GP_BSZ + brr[u]*136 + bsg[u])*4,
                  vt + (size_t)(bnn[u]*Ll + j0 + brr[u])*Dd + h*DHh + bdd[u]);
        }
        CP_COMMIT();
    };

    float acc[2][8][4] = {};
    prefetch(0, 0); prefetch(1, 1);
    for (int jt = 0; jt < 12; jt++) {
        if (jt < 11) CP_WAIT1(); else CP_WAIT0();
        __syncthreads();
        const uint32_t* Ab = Asm + (jt&1)*GP_ASZ;
        const uint32_t* Bb = Bsm + (jt&1)*GP_BSZ;
        #pragma unroll
        for (int kk = 0; kk < 4; kk++) {
            int kb = kk * 8;
            uint32_t a[2][4];
            #pragma unroll
            for (int mf = 0; mf < 2; mf++) {
                int r = wm0 + mf*16 + gid;
                a[mf][0] = Ab[r*36 + kb + tig];
                a[mf][1] = Ab[(r+8)*36 + kb + tig];
                a[mf][2] = Ab[r*36 + kb + tig + 4];
                a[mf][3] = Ab[(r+8)*36 + kb + tig + 4];
            }
            uint32_t b[8][2];
            #pragma unroll
            for (int nf = 0; nf < 8; nf++) {
                int cn = wn0 + nf*8 + gid;
                b[nf][0] = Bb[(kb+tig)*136 + cn];
                b[nf][1] = Bb[(kb+tig+4)*136 + cn];
            }
            #pragma unroll
            for (int mf = 0; mf < 2; mf++)
                #pragma unroll
                for (int nf = 0; nf < 8; nf++)
                    mma_tf32(acc[mf][nf][0], acc[mf][nf][1], acc[mf][nf][2], acc[mf][nf][3],
                             a[mf][0], a[mf][1], a[mf][2], a[mf][3],
                             b[nf][0], b[nf][1]);
        }
        __syncthreads();
        if (jt + 2 < 12) prefetch(jt+2, jt&1);
    }
    #pragma unroll
    for (int mf = 0; mf < 2; mf++) {
        #pragma unroll
        for (int half = 0; half < 2; half++) {
            int i = i0 + wm0 + mf*16 + gid + half*8;
            #pragma unroll
            for (int nf = 0; nf < 8; nf++) {
                int cg = c0 + wn0 + nf*8 + tig*2;
                int nn = cg >> 5, dd = cg & 31;
                size_t idx = (size_t)(nn*Ll + i)*Dd + h*DHh + dd;
                float2 gt = *(const float2*)(gate + idx);
                uint2 ov;
                ov.x = f2tf32(acc[mf][nf][half*2 + 0] * gt.x);
                ov.y = f2tf32(acc[mf][nf][half*2 + 1] * gt.y);
                *(uint2*)(o + idx) = ov;
            }
        }
    }
}

// ---------------- host launch ----------------
extern "C" void kernel_launch(void* const* d_in, const int* in_sizes, int n_in,
                              void* d_out, int out_size) {
    const float* msa       = (const float*)d_in[0];
    const float* pair      = (const float*)d_in[1];
    const float* ln_msa_g  = (const float*)d_in[2];
    const float* ln_msa_b  = (const float*)d_in[3];
    const float* ln_pair_g = (const float*)d_in[4];
    const float* ln_pair_b = (const float*)d_in[5];
    const float* Wq_sw     = (const float*)d_in[6];
    const float* bq_sw     = (const float*)d_in[7];
    const float* Wk_sw     = (const float*)d_in[8];
    const float* bk_sw     = (const float*)d_in[9];
    const float* Wq        = (const float*)d_in[10];
    const float* Wk        = (const float*)d_in[11];
    const float* Wv        = (const float*)d_in[12];
    const float* Wb        = (const float*)d_in[13];
    const float* Wg        = (const float*)d_in[14];
    const float* bg        = (const float*)d_in[15];
    const float* Wo        = (const float*)d_in[16];
    const float* bo        = (const float*)d_in[17];
    float* out = (float*)d_out;

    uint32_t *mt_, *qt_, *kt_, *vt_, *ot_, *wt_;
    float *gg_, *qsw_, *sw_, *lg_, *bi_;
    cudaGetSymbolAddress((void**)&mt_,  g_mt);
    cudaGetSymbolAddress((void**)&qt_,  g_qt);
    cudaGetSymbolAddress((void**)&kt_,  g_kt);
    cudaGetSymbolAddress((void**)&vt_,  g_vt);
    cudaGetSymbolAddress((void**)&ot_,  g_ot);
    cudaGetSymbolAddress((void**)&wt_,  g_wt);
    cudaGetSymbolAddress((void**)&gg_,  g_g);
    cudaGetSymbolAddress((void**)&qsw_, g_qsw);
    cudaGetSymbolAddress((void**)&sw_,  g_sw);
    cudaGetSymbolAddress((void**)&lg_,  g_logits);
    cudaGetSymbolAddress((void**)&bi_,  g_bias);

    cudaFuncSetAttribute(gemmP<true,false,false,false,false>,  cudaFuncAttributeMaxDynamicSharedMemorySize, GP_SMEM);
    cudaFuncSetAttribute(gemmP<true,false,true,false,false>,   cudaFuncAttributeMaxDynamicSharedMemorySize, GP_SMEM);
    cudaFuncSetAttribute(gemmP<false,false,false,true,true>,   cudaFuncAttributeMaxDynamicSharedMemorySize, GP_SMEM);
    cudaFuncSetAttribute(gemmP<false,false,false,false,true>,  cudaFuncAttributeMaxDynamicSharedMemorySize, GP_SMEM);
    cudaFuncSetAttribute(gemmP<true,true,false,false,false>,   cudaFuncAttributeMaxDynamicSharedMemorySize, GP_SMEM);
    cudaFuncSetAttribute(logitsP, cudaFuncAttributeMaxDynamicSharedMemorySize, LG_SMEM);
    cudaFuncSetAttribute(outP,    cudaFuncAttributeMaxDynamicSharedMemorySize, GP_SMEM);

    dim3 gproj(2, NL/128);
    const int WSZ = Dd*Dd;

    // 1. LN(msa) -> tf32
    ln_tf32_kernel<<<NL, 256>>>(msa, ln_msa_g, ln_msa_b, mt_);
    // 2. weights -> tf32
    wconv_kernel<<<WSZ/256, 256>>>(Wq_sw, wt_ + 0*WSZ);
    wconv_kernel<<<WSZ/256, 256>>>(Wk_sw, wt_ + 1*WSZ);
    wconv_kernel<<<WSZ/256, 256>>>(Wq,    wt_ + 2*WSZ);
    wconv_kernel<<<WSZ/256, 256>>>(Wk,    wt_ + 3*WSZ);
    wconv_kernel<<<WSZ/256, 256>>>(Wv,    wt_ + 4*WSZ);
    wconv_kernel<<<WSZ/256, 256>>>(Wg,    wt_ + 5*WSZ);
    wconv_kernel<<<WSZ/256, 256>>>(Wo,    wt_ + 6*WSZ);
    // 3. q_sw = (LN(msa[n=0]) @ Wq_sw + bq_sw) * scale
    gemmP<true,false,false,false,false><<<dim3(2,3), 256, GP_SMEM>>>(
        mt_, wt_ + 0*WSZ, bq_sw, nullptr, nullptr, nullptr, SCALE, qsw_, nullptr);
    // 4. sw_logits = (LN(msa) @ Wk_sw + bk_sw) . qsw
    gemmP<true,false,true,false,false><<<gproj, 256, GP_SMEM>>>(
        mt_, wt_ + 1*WSZ, bk_sw, qsw_, sw_, nullptr, 1.f, nullptr, nullptr);
    // 5. softmax over n -> seq_weight
    swsoftmax_kernel<<<Ll*Hh, 256>>>(sw_);
    // 6. q = (LN(msa) @ Wq) * seq_weight, tf32
    gemmP<false,false,false,true,true><<<gproj, 256, GP_SMEM>>>(
        mt_, wt_ + 2*WSZ, nullptr, nullptr, nullptr, sw_, 1.f, nullptr, qt_);
    // 7. k = (LN(msa) @ Wk) * scale, tf32
    gemmP<false,false,false,false,true><<<gproj, 256, GP_SMEM>>>(
        mt_, wt_ + 3*WSZ, nullptr, nullptr, nullptr, nullptr, SCALE, nullptr, kt_);
    // 8. v = LN(msa) @ Wv, tf32
    gemmP<false,false,false,false,true><<<gproj, 256, GP_SMEM>>>(
        mt_, wt_ + 4*WSZ, nullptr, nullptr, nullptr, nullptr, 1.f, nullptr, vt_);
    // 9. gate = sigmoid(LN(msa) @ Wg + bg), fp32
    gemmP<true,true,false,false,false><<<gproj, 256, GP_SMEM>>>(
        mt_, wt_ + 5*WSZ, bg, nullptr, nullptr, nullptr, 1.f, gg_, nullptr);
    // 10. pair bias
    pairbias_kernel<<<LLp, 128>>>(pair, ln_pair_g, ln_pair_b, Wb, bi_);
    // 11. logits (+bias)
    logitsP<<<dim3(3,3,8), 256, LG_SMEM>>>(qt_, kt_, bi_, lg_);
    // 12. attn = softmax(logits), tf32 in place
    attnsoftmax_kernel<<<Hh*Ll, Ll>>>(lg_);
    // 13. out = (attn @ v) * gate, tf32
    outP<<<dim3((Nn*DHh)/128, 3, 8), 256, GP_SMEM>>>((uint32_t*)lg_, vt_, gg_, ot_);
    // 14. y = out @ Wo + bo
    gemmP<true,false,false,false,false><<<dim3(2, NL/128), 256, GP_SMEM>>>(
        ot_, wt_ + 6*WSZ, bo, nullptr, nullptr, nullptr, 1.f, out, nullptr);
}

// round 13
// speedup vs baseline: 1.5053x; 1.5053x over previous
#include <cuda_runtime.h>
#include <math.h>
#include <stdint.h>

// Problem constants
#define Nn   256
#define Ll   384
#define Dd   256
#define DP   128
#define Hh   8
#define DHh  32
#define NL   (Nn*Ll)      // 98304 rows
#define LLp  (Ll*Ll)      // 147456
#define EPSF 1e-5f
#define SCALE 0.17677669529663687f  // 1/sqrt(32)

// ---------------- scratch (device globals; no allocation allowed) ----------------
__device__ uint32_t g_mt [NL*Dd];   // LN(msa) in tf32
__device__ uint32_t g_qt [NL*Dd];   // q * seq_weight, tf32
__device__ uint32_t g_kt [NL*Dd];   // k * scale, tf32
__device__ uint32_t g_vt [NL*Dd];   // v, tf32
__device__ float    g_g  [NL*Dd];   // gate (fp32)
__device__ uint32_t g_ot [NL*Dd];   // (attn@v)*gate, tf32
__device__ float    g_qsw[Ll*Dd];   // seq-weight queries (fp32)
__device__ float    g_sw [NL*Hh];   // sw logits -> seq weights
__device__ float    g_logits[Hh*LLp]; // logits(+bias) fp32 -> attn tf32 (in place)
__device__ float    g_bias  [Hh*LLp]; // pair bias
__device__ uint32_t g_wt [7*Dd*Dd];  // tf32 weights: Wq_sw,Wk_sw,Wq,Wk,Wv,Wg,Wo

// ---------------- helpers ----------------
__device__ __forceinline__ uint32_t f2tf32(float f) {
    uint32_t r;
    asm("cvt.rna.tf32.f32 %0, %1;" : "=r"(r) : "f"(f));
    return r;
}

__device__ __forceinline__ void mma_tf32(float& c0, float& c1, float& c2, float& c3,
                                         uint32_t a0, uint32_t a1, uint32_t a2, uint32_t a3,
                                         uint32_t b0, uint32_t b1) {
    asm volatile("mma.sync.aligned.m16n8k8.row.col.f32.tf32.tf32.f32 "
                 "{%0,%1,%2,%3}, {%4,%5,%6,%7}, {%8,%9}, {%0,%1,%2,%3};"
                 : "+f"(c0), "+f"(c1), "+f"(c2), "+f"(c3)
                 : "r"(a0), "r"(a1), "r"(a2), "r"(a3), "r"(b0), "r"(b1));
}

__device__ __forceinline__ void cpa16(uint32_t smem, const void* gmem) {
    asm volatile("cp.async.cg.shared.global [%0], [%1], 16;" :: "r"(smem), "l"(gmem));
}
#define CP_COMMIT() asm volatile("cp.async.commit_group;")
#define CP_WAIT1()  asm volatile("cp.async.wait_group 1;")
#define CP_WAIT0()  asm volatile("cp.async.wait_group 0;")

// ---------------- LayerNorm msa -> tf32 (one row per block) ----------------
__global__ void ln_tf32_kernel(const float* __restrict__ x, const float* __restrict__ g,
                               const float* __restrict__ b, uint32_t* __restrict__ out) {
    __shared__ float s1[8], s2[8];
    __shared__ float mu_s, rs_s;
    int row = blockIdx.x;
    int t = threadIdx.x;
    float v = x[(size_t)row*Dd + t];
    float s = v, q = v*v;
    #pragma unroll
    for (int o = 16; o; o >>= 1) {
        s += __shfl_down_sync(0xffffffffu, s, o);
        q += __shfl_down_sync(0xffffffffu, q, o);
    }
    int lane = t & 31, w = t >> 5;
    if (!lane) { s1[w] = s; s2[w] = q; }
    __syncthreads();
    if (w == 0) {
        float ss = (lane < 8) ? s1[lane] : 0.f;
        float qq = (lane < 8) ? s2[lane] : 0.f;
        #pragma unroll
        for (int o = 16; o; o >>= 1) {
            ss += __shfl_down_sync(0xffffffffu, ss, o);
            qq += __shfl_down_sync(0xffffffffu, qq, o);
        }
        if (!lane) {
            float mu = ss * (1.0f/Dd);
            float var = qq * (1.0f/Dd) - mu*mu;
            mu_s = mu;
            rs_s = rsqrtf(var + EPSF);
        }
    }
    __syncthreads();
    out[(size_t)row*Dd + t] = f2tf32((v - mu_s) * rs_s * g[t] + b[t]);
}

// ---------------- all 7 weights fp32 -> tf32 (one launch) ----------------
__global__ void wconv_kernel(const float* __restrict__ w0, const float* __restrict__ w1,
                             const float* __restrict__ w2, const float* __restrict__ w3,
                             const float* __restrict__ w4, const float* __restrict__ w5,
                             const float* __restrict__ w6, uint32_t* __restrict__ dst) {
    int i = blockIdx.x*256 + threadIdx.x;      // 0 .. 7*65536-1
    int m = i >> 16, r = i & 0xFFFF;
    const float* src = (m==0)?w0:(m==1)?w1:(m==2)?w2:(m==3)?w3:(m==4)?w4:(m==5)?w5:w6;
    dst[i] = f2tf32(src[r]);
}

// ============================================================================
// Pure TF32 GEMM, cp.async double-buffered. C[Mx256] = A[tf32] @ B[tf32].
// BM=128, BN=128, BK=32, 256 threads (8 warps 4x2). No occupancy clamp.
// Epilogue flags: BIAS(+bias), SIG(sigmoid), SWL(sw_logits dot, no C store),
// SWMUL(*swp[row][col>>5]), TF32OUT(store tf32 to Ct else fp32 to Cf).
// ============================================================================
#define GP_ASZ (128*36)
#define GP_BSZ (32*136)
#define GP_SMEM ((2*GP_ASZ + 2*GP_BSZ)*4)

template<bool BIAS, bool SIG, bool SWL, bool SWMUL, bool TF32OUT>
__global__ void __launch_bounds__(256) gemmP(
        const uint32_t* __restrict__ A, const uint32_t* __restrict__ B,
        const float* __restrict__ bias, const float* __restrict__ qsw,
        float* __restrict__ swl, const float* __restrict__ swp,
        float scale, float* __restrict__ Cf, uint32_t* __restrict__ Ct) {
    extern __shared__ uint32_t sh[];
    uint32_t* Asm = sh;
    uint32_t* Bsm = sh + 2*GP_ASZ;
    uint32_t sA0 = (uint32_t)__cvta_generic_to_shared(Asm);
    uint32_t sB0 = (uint32_t)__cvta_generic_to_shared(Bsm);
    int tid = threadIdx.x;
    int wid = tid >> 5, lane = tid & 31;
    int gid = lane >> 2, tig = lane & 3;
    int wm0 = (wid >> 1) * 32;
    int wn0 = (wid & 1) * 64;
    int m0 = blockIdx.y * 128, n0 = blockIdx.x * 128;

    int ar[4], ac[4], br[4], bc[4];
    #pragma unroll
    for (int u = 0; u < 4; u++) {
        int f = tid + u*256;
        ar[u] = f >> 3; ac[u] = (f & 7) * 4;
        br[u] = f >> 5; bc[u] = (f & 31) * 4;
    }
    auto prefetch = [&](int kt, int buf) {
        #pragma unroll
        for (int u = 0; u < 4; u++) {
            cpa16(sA0 + (uint32_t)(buf*GP_ASZ + ar[u]*36 + ac[u])*4,
                  A + (size_t)(m0+ar[u])*Dd + kt*32 + ac[u]);
            cpa16(sB0 + (uint32_t)(buf*GP_BSZ + br[u]*136 + bc[u])*4,
                  B + (size_t)(kt*32+br[u])*Dd + n0 + bc[u]);
        }
        CP_COMMIT();
    };

    float acc[2][8][4] = {};
    prefetch(0, 0); prefetch(1, 1);
    for (int kt = 0; kt < 8; kt++) {
        if (kt < 7) CP_WAIT1(); else CP_WAIT0();
        __syncthreads();
        const uint32_t* Ab = Asm + (kt&1)*GP_ASZ;
        const uint32_t* Bb = Bsm + (kt&1)*GP_BSZ;
        #pragma unroll
        for (int kk = 0; kk < 4; kk++) {
            int kb = kk * 8;
            uint32_t a[2][4];
            #pragma unroll
            for (int mf = 0; mf < 2; mf++) {
                int r = wm0 + mf*16 + gid;
                a[mf][0] = Ab[r*36 + kb + tig];
                a[mf][1] = Ab[(r+8)*36 + kb + tig];
                a[mf][2] = Ab[r*36 + kb + tig + 4];
                a[mf][3] = Ab[(r+8)*36 + kb + tig + 4];
            }
            uint32_t b[8][2];
            #pragma unroll
            for (int nf = 0; nf < 8; nf++) {
                int cn = wn0 + nf*8 + gid;
                b[nf][0] = Bb[(kb+tig)*136 + cn];
                b[nf][1] = Bb[(kb+tig+4)*136 + cn];
            }
            #pragma unroll
            for (int mf = 0; mf < 2; mf++)
                #pragma unroll
                for (int nf = 0; nf < 8; nf++)
                    mma_tf32(acc[mf][nf][0], acc[mf][nf][1], acc[mf][nf][2], acc[mf][nf][3],
                             a[mf][0], a[mf][1], a[mf][2], a[mf][3],
                             b[nf][0], b[nf][1]);
        }
        __syncthreads();
        if (kt + 2 < 8) prefetch(kt+2, kt&1);
    }

    if (SWL) {
        #pragma unroll
        for (int mf = 0; mf < 2; mf++) {
            #pragma unroll
            for (int half = 0; half < 2; half++) {
                int row = m0 + wm0 + mf*16 + gid + half*8;
                int i = row % Ll;
                float p0 = 0.f, p1 = 0.f;
                #pragma unroll
                for (int nf = 0; nf < 8; nf++) {
                    int col = n0 + wn0 + nf*8 + tig*2;
                    float v0 = acc[mf][nf][half*2 + 0] + bias[col];
                    float v1 = acc[mf][nf][half*2 + 1] + bias[col+1];
                    float2 qv = *(const float2*)(qsw + (size_t)i*Dd + col);
                    float contrib = v0*qv.x + v1*qv.y;
                    if (nf < 4) p0 += contrib; else p1 += contrib;
                }
                p0 += __shfl_xor_sync(0xffffffffu, p0, 1);
                p0 += __shfl_xor_sync(0xffffffffu, p0, 2);
                p1 += __shfl_xor_sync(0xffffffffu, p1, 1);
                p1 += __shfl_xor_sync(0xffffffffu, p1, 2);
                if (tig == 0) {
                    int h0 = (n0 + wn0) >> 5;
                    swl[(size_t)row*Hh + h0]     = p0;
                    swl[(size_t)row*Hh + h0 + 1] = p1;
                }
            }
        }
    } else {
        #pragma unroll
        for (int mf = 0; mf < 2; mf++) {
            #pragma unroll
            for (int half = 0; half < 2; half++) {
                int row = m0 + wm0 + mf*16 + gid + half*8;
                #pragma unroll
                for (int nf = 0; nf < 8; nf++) {
                    int col = n0 + wn0 + nf*8 + tig*2;
                    float v0 = acc[mf][nf][half*2 + 0];
                    float v1 = acc[mf][nf][half*2 + 1];
                    if (BIAS) { v0 += bias[col]; v1 += bias[col+1]; }
                    v0 *= scale; v1 *= scale;
                    if (SIG) {
                        v0 = 1.f / (1.f + expf(-v0));
                        v1 = 1.f / (1.f + expf(-v1));
                    }
                    if (SWMUL) {
                        float swv = swp[(size_t)row*Hh + (col >> 5)];
                        v0 *= swv; v1 *= swv;
                    }
                    if (TF32OUT) {
                        uint2 o; o.x = f2tf32(v0); o.y = f2tf32(v1);
                        *(uint2*)(Ct + (size_t)row*Dd + col) = o;
                    } else {
                        float2 o; o.x = v0; o.y = v1;
                        *(float2*)(Cf + (size_t)row*Dd + col) = o;
                    }
                }
            }
        }
    }
}

// ---------------- softmax over n (256) for each (i,h) ----------------
__global__ void swsoftmax_kernel(float* __restrict__ sw) {
    __shared__ float sm[8];
    __shared__ float red;
    int ih = blockIdx.x;
    int n = threadIdx.x;
    int lane = n & 31, w = n >> 5;
    float v = sw[(size_t)n*(Ll*Hh) + ih];
    float mx = v;
    #pragma unroll
    for (int o = 16; o; o >>= 1) mx = fmaxf(mx, __shfl_down_sync(0xffffffffu, mx, o));
    if (!lane) sm[w] = mx;
    __syncthreads();
    if (w == 0) {
        float x = (lane < 8) ? sm[lane] : -3.4e38f;
        #pragma unroll
        for (int o = 16; o; o >>= 1) x = fmaxf(x, __shfl_down_sync(0xffffffffu, x, o));
        if (!lane) red = x;
    }
    __syncthreads();
    mx = red;
    float e = expf(v - mx);
    float s = e;
    #pragma unroll
    for (int o = 16; o; o >>= 1) s += __shfl_down_sync(0xffffffffu, s, o);
    __syncthreads();
    if (!lane) sm[w] = s;
    __syncthreads();
    if (w == 0) {
        float x = (lane < 8) ? sm[lane] : 0.f;
        #pragma unroll
        for (int o = 16; o; o >>= 1) x += __shfl_down_sync(0xffffffffu, x, o);
        if (!lane) red = x;
    }
    __syncthreads();
    sw[(size_t)n*(Ll*Hh) + ih] = e / red;
}

// ---------------- pair bias: LN(pair row) @ Wb -> bias[h][i][j] ----------------
__global__ void pairbias_kernel(const float* __restrict__ pair, const float* __restrict__ g,
                                const float* __restrict__ b, const float* __restrict__ Wb,
                                float* __restrict__ bias) {
    __shared__ float s1[4], s2[4];
    __shared__ float hp[4][8];
    int ij = blockIdx.x;
    int t = threadIdx.x;
    int lane = t & 31, w = t >> 5;
    float v = pair[(size_t)ij*DP + t];
    float s = v, q = v*v;
    #pragma unroll
    for (int o = 16; o; o >>= 1) {
        s += __shfl_down_sync(0xffffffffu, s, o);
        q += __shfl_down_sync(0xffffffffu, q, o);
    }
    if (!lane) { s1[w] = s; s2[w] = q; }
    __syncthreads();
    if (w == 0) {
        float ss = (lane < 4) ? s1[lane] : 0.f;
        float qq = (lane < 4) ? s2[lane] : 0.f;
        #pragma unroll
        for (int o = 16; o; o >>= 1) {
            ss += __shfl_down_sync(0xffffffffu, ss, o);
            qq += __shfl_down_sync(0xffffffffu, qq, o);
        }
        if (!lane) { s1[0] = ss; s2[0] = qq; }
    }
    __syncthreads();
    float mu = s1[0] * (1.0f/DP);
    float var = s2[0] * (1.0f/DP) - mu*mu;
    float ln = (v - mu) * rsqrtf(var + EPSF) * g[t] + b[t];
    float p[8];
    #pragma unroll
    for (int h = 0; h < 8; h++) p[h] = ln * Wb[t*Hh + h];
    #pragma unroll
    for (int h = 0; h < 8; h++)
        #pragma unroll
        for (int o = 16; o; o >>= 1) p[h] += __shfl_down_sync(0xffffffffu, p[h], o);
    if (!lane) {
        #pragma unroll
        for (int h = 0; h < 8; h++) hp[w][h] = p[h];
    }
    __syncthreads();
    if (t < 8) {
        float x = hp[0][t] + hp[1][t] + hp[2][t] + hp[3][t];
        bias[(size_t)t*LLp + ij] = x;
    }
}

// ============================================================================
// Pure TF32 logits 128x128, cp.async double-buffered over n.
// logits[h][i][j] = sum_{n,d} qt[n,i,h,d]*kt[n,j,h,d] + bias
// grid (3, 3, 8), 256 threads.
// ============================================================================
#define LG_TSZ (128*36)
#define LG_SMEM (4*LG_TSZ*4)

__global__ void __launch_bounds__(256) logitsP(
        const uint32_t* __restrict__ qt, const uint32_t* __restrict__ ktm,
        const float* __restrict__ bias, float* __restrict__ out) {
    extern __shared__ uint32_t sh[];
    uint32_t* Asm = sh;
    uint32_t* Bsm = sh + 2*LG_TSZ;
    uint32_t sA0 = (uint32_t)__cvta_generic_to_shared(Asm);
    uint32_t sB0 = (uint32_t)__cvta_generic_to_shared(Bsm);
    int h = blockIdx.z;
    int i0 = blockIdx.y * 128, j0 = blockIdx.x * 128;
    int tid = threadIdx.x;
    int wid = tid >> 5, lane = tid & 31;
    int gid = lane >> 2, tig = lane & 3;
    int wm0 = (wid >> 1) * 32;
    int wn0 = (wid & 1) * 64;

    int lr[4], lc[4];
    #pragma unroll
    for (int u = 0; u < 4; u++) {
        int f = tid + u*256;
        lr[u] = f >> 3; lc[u] = (f & 7) * 4;
    }
    auto prefetch = [&](int n, int buf) {
        #pragma unroll
        for (int u = 0; u < 4; u++) {
            cpa16(sA0 + (uint32_t)(buf*LG_TSZ + lr[u]*36 + lc[u])*4,
                  qt + (size_t)(n*Ll + i0 + lr[u])*Dd + h*DHh + lc[u]);
            cpa16(sB0 + (uint32_t)(buf*LG_TSZ + lr[u]*36 + lc[u])*4,
                  ktm + (size_t)(n*Ll + j0 + lr[u])*Dd + h*DHh + lc[u]);
        }
        CP_COMMIT();
    };

    float acc[2][8][4] = {};
    prefetch(0, 0); prefetch(1, 1);
    for (int n = 0; n < Nn; n++) {
        if (n < Nn-1) CP_WAIT1(); else CP_WAIT0();
        __syncthreads();
        const uint32_t* Ab = Asm + (n&1)*LG_TSZ;
        const uint32_t* Bb = Bsm + (n&1)*LG_TSZ;
        #pragma unroll
        for (int kk = 0; kk < 4; kk++) {
            int kb = kk * 8;
            uint32_t a[2][4];
            #pragma unroll
            for (int mf = 0; mf < 2; mf++) {
                int r = wm0 + mf*16 + gid;
                a[mf][0] = Ab[r*36 + kb + tig];
                a[mf][1] = Ab[(r+8)*36 + kb + tig];
                a[mf][2] = Ab[r*36 + kb + tig + 4];
                a[mf][3] = Ab[(r+8)*36 + kb + tig + 4];
            }
            uint32_t b[8][2];
            #pragma unroll
            for (int nf = 0; nf < 8; nf++) {
                int cn = wn0 + nf*8 + gid;
                b[nf][0] = Bb[cn*36 + kb + tig];
                b[nf][1] = Bb[cn*36 + kb + tig + 4];
            }
            #pragma unroll
            for (int mf = 0; mf < 2; mf++)
                #pragma unroll
                for (int nf = 0; nf < 8; nf++)
                    mma_tf32(acc[mf][nf][0], acc[mf][nf][1], acc[mf][nf][2], acc[mf][nf][3],
                             a[mf][0], a[mf][1], a[mf][2], a[mf][3],
                             b[nf][0], b[nf][1]);
        }
        __syncthreads();
        if (n + 2 < Nn) prefetch(n+2, n&1);
    }
    #pragma unroll
    for (int mf = 0; mf < 2; mf++) {
        #pragma unroll
        for (int half = 0; half < 2; half++) {
            int i = i0 + wm0 + mf*16 + gid + half*8;
            #pragma unroll
            for (int nf = 0; nf < 8; nf++) {
                int j = j0 + wn0 + nf*8 + tig*2;
                size_t idx = (size_t)h*LLp + (size_t)i*Ll + j;
                float2 bb = *(const float2*)(bias + idx);
                float2 o;
                o.x = acc[mf][nf][half*2 + 0] + bb.x;
                o.y = acc[mf][nf][half*2 + 1] + bb.y;
                *(float2*)(out + idx) = o;
            }
        }
    }
}

// ---------------- softmax over j (384), writes tf32 for attn@v ----------------
__global__ void attnsoftmax_kernel(float* __restrict__ logits) {
    __shared__ float sm[12];
    __shared__ float red;
    int hi = blockIdx.x;
    size_t base = (size_t)hi * Ll;
    int j = threadIdx.x;
    int lane = j & 31, w = j >> 5;
    float v = logits[base + j];
    float mx = v;
    #pragma unroll
    for (int o = 16; o; o >>= 1) mx = fmaxf(mx, __shfl_down_sync(0xffffffffu, mx, o));
    if (!lane) sm[w] = mx;
    __syncthreads();
    if (w == 0) {
        float x = (lane < 12) ? sm[lane] : -3.4e38f;
        #pragma unroll
        for (int o = 16; o; o >>= 1) x = fmaxf(x, __shfl_down_sync(0xffffffffu, x, o));
        if (!lane) red = x;
    }
    __syncthreads();
    mx = red;
    float e = expf(v - mx);
    float s = e;
    #pragma unroll
    for (int o = 16; o; o >>= 1) s += __shfl_down_sync(0xffffffffu, s, o);
    __syncthreads();
    if (!lane) sm[w] = s;
    __syncthreads();
    if (w == 0) {
        float x = (lane < 12) ? sm[lane] : 0.f;
        #pragma unroll
        for (int o = 16; o; o >>= 1) x += __shfl_down_sync(0xffffffffu, x, o);
        if (!lane) red = x;
    }
    __syncthreads();
    ((uint32_t*)logits)[base + j] = f2tf32(e / red);
}

// ============================================================================
// Pure TF32 attn@V 128x128, cp.async double-buffered, fused gate.
// out = (attn @ v) * gate, stored tf32. grid (64, 3, 8).
// ============================================================================
__global__ void __launch_bounds__(256) outP(
        const uint32_t* __restrict__ attn, const uint32_t* __restrict__ vt,
        const float* __restrict__ gate, uint32_t* __restrict__ o) {
    extern __shared__ uint32_t sh[];
    uint32_t* Asm = sh;
    uint32_t* Bsm = sh + 2*GP_ASZ;
    uint32_t sA0 = (uint32_t)__cvta_generic_to_shared(Asm);
    uint32_t sB0 = (uint32_t)__cvta_generic_to_shared(Bsm);
    int h = blockIdx.z;
    int i0 = blockIdx.y * 128, c0 = blockIdx.x * 128;
    int tid = threadIdx.x;
    int wid = tid >> 5, lane = tid & 31;
    int gid = lane >> 2, tig = lane & 3;
    int wm0 = (wid >> 1) * 32;
    int wn0 = (wid & 1) * 64;

    int ar[4], ac[4], brr[4], bsg[4], bnn[4], bdd[4];
    #pragma unroll
    for (int u = 0; u < 4; u++) {
        int f = tid + u*256;
        ar[u] = f >> 3; ac[u] = (f & 7) * 4;
        brr[u] = f >> 5;
        int seg = f & 31;
        bsg[u] = seg * 4;
        int cg = c0 + seg*4;
        bnn[u] = cg >> 5; bdd[u] = cg & 31;
    }
    auto prefetch = [&](int jt, int buf) {
        int j0 = jt * 32;
        #pragma unroll
        for (int u = 0; u < 4; u++) {
            cpa16(sA0 + (uint32_t)(buf*GP_ASZ + ar[u]*36 + ac[u])*4,
                  attn + (size_t)h*LLp + (size_t)(i0 + ar[u])*Ll + j0 + ac[u]);
            cpa16(sB0 + (uint32_t)(buf*GP_BSZ + brr[u]*136 + bsg[u])*4,
                  vt + (size_t)(bnn[u]*Ll + j0 + brr[u])*Dd + h*DHh + bdd[u]);
        }
        CP_COMMIT();
    };

    float acc[2][8][4] = {};
    prefetch(0, 0); prefetch(1, 1);
    for (int jt = 0; jt < 12; jt++) {
        if (jt < 11) CP_WAIT1(); else CP_WAIT0();
        __syncthreads();
        const uint32_t* Ab = Asm + (jt&1)*GP_ASZ;
        const uint32_t* Bb = Bsm + (jt&1)*GP_BSZ;
        #pragma unroll
        for (int kk = 0; kk < 4; kk++) {
            int kb = kk * 8;
            uint32_t a[2][4];
            #pragma unroll
            for (int mf = 0; mf < 2; mf++) {
                int r = wm0 + mf*16 + gid;
                a[mf][0] = Ab[r*36 + kb + tig];
                a[mf][1] = Ab[(r+8)*36 + kb + tig];
                a[mf][2] = Ab[r*36 + kb + tig + 4];
                a[mf][3] = Ab[(r+8)*36 + kb + tig + 4];
            }
            uint32_t b[8][2];
            #pragma unroll
            for (int nf = 0; nf < 8; nf++) {
                int cn = wn0 + nf*8 + gid;
                b[nf][0] = Bb[(kb+tig)*136 + cn];
                b[nf][1] = Bb[(kb+tig+4)*136 + cn];
            }
            #pragma unroll
            for (int mf = 0; mf < 2; mf++)
                #pragma unroll
                for (int nf = 0; nf < 8; nf++)
                    mma_tf32(acc[mf][nf][0], acc[mf][nf][1], acc[mf][nf][2], acc[mf][nf][3],
                             a[mf][0], a[mf][1], a[mf][2], a[mf][3],
                             b[nf][0], b[nf][1]);
        }
        __syncthreads();
        if (jt + 2 < 12) prefetch(jt+2, jt&1);
    }
    #pragma unroll
    for (int mf = 0; mf < 2; mf++) {
        #pragma unroll
        for (int half = 0; half < 2; half++) {
            int i = i0 + wm0 + mf*16 + gid + half*8;
            #pragma unroll
            for (int nf = 0; nf < 8; nf++) {
                int cg = c0 + wn0 + nf*8 + tig*2;
                int nn = cg >> 5, dd = cg & 31;
                size_t idx = (size_t)(nn*Ll + i)*Dd + h*DHh + dd;
                float2 gt = *(const float2*)(gate + idx);
                uint2 ov;
                ov.x = f2tf32(acc[mf][nf][half*2 + 0] * gt.x);
                ov.y = f2tf32(acc[mf][nf][half*2 + 1] * gt.y);
                *(uint2*)(o + idx) = ov;
            }
        }
    }
}

// ---------------- host launch ----------------
extern "C" void kernel_launch(void* const* d_in, const int* in_sizes, int n_in,
                              void* d_out, int out_size) {
    const float* msa       = (const float*)d_in[0];
    const float* pair      = (const float*)d_in[1];
    const float* ln_msa_g  = (const float*)d_in[2];
    const float* ln_msa_b  = (const float*)d_in[3];
    const float* ln_pair_g = (const float*)d_in[4];
    const float* ln_pair_b = (const float*)d_in[5];
    const float* Wq_sw     = (const float*)d_in[6];
    const float* bq_sw     = (const float*)d_in[7];
    const float* Wk_sw     = (const float*)d_in[8];
    const float* bk_sw     = (const float*)d_in[9];
    const float* Wq        = (const float*)d_in[10];
    const float* Wk        = (const float*)d_in[11];
    const float* Wv        = (const float*)d_in[12];
    const float* Wb        = (const float*)d_in[13];
    const float* Wg        = (const float*)d_in[14];
    const float* bg        = (const float*)d_in[15];
    const float* Wo        = (const float*)d_in[16];
    const float* bo        = (const float*)d_in[17];
    float* out = (float*)d_out;

    uint32_t *mt_, *qt_, *kt_, *vt_, *ot_, *wt_;
    float *gg_, *qsw_, *sw_, *lg_, *bi_;
    cudaGetSymbolAddress((void**)&mt_,  g_mt);
    cudaGetSymbolAddress((void**)&qt_,  g_qt);
    cudaGetSymbolAddress((void**)&kt_,  g_kt);
    cudaGetSymbolAddress((void**)&vt_,  g_vt);
    cudaGetSymbolAddress((void**)&ot_,  g_ot);
    cudaGetSymbolAddress((void**)&wt_,  g_wt);
    cudaGetSymbolAddress((void**)&gg_,  g_g);
    cudaGetSymbolAddress((void**)&qsw_, g_qsw);
    cudaGetSymbolAddress((void**)&sw_,  g_sw);
    cudaGetSymbolAddress((void**)&lg_,  g_logits);
    cudaGetSymbolAddress((void**)&bi_,  g_bias);

    cudaFuncSetAttribute(gemmP<true,false,false,false,false>,  cudaFuncAttributeMaxDynamicSharedMemorySize, GP_SMEM);
    cudaFuncSetAttribute(gemmP<true,false,true,false,false>,   cudaFuncAttributeMaxDynamicSharedMemorySize, GP_SMEM);
    cudaFuncSetAttribute(gemmP<false,false,false,true,true>,   cudaFuncAttributeMaxDynamicSharedMemorySize, GP_SMEM);
    cudaFuncSetAttribute(gemmP<false,false,false,false,true>,  cudaFuncAttributeMaxDynamicSharedMemorySize, GP_SMEM);
    cudaFuncSetAttribute(gemmP<true,true,false,false,false>,   cudaFuncAttributeMaxDynamicSharedMemorySize, GP_SMEM);
    cudaFuncSetAttribute(logitsP, cudaFuncAttributeMaxDynamicSharedMemorySize, LG_SMEM);
    cudaFuncSetAttribute(outP,    cudaFuncAttributeMaxDynamicSharedMemorySize, GP_SMEM);

    dim3 gproj(2, NL/128);
    const int WSZ = Dd*Dd;

    // 1. LN(msa) -> tf32
    ln_tf32_kernel<<<NL, 256>>>(msa, ln_msa_g, ln_msa_b, mt_);
    // 2. all weights -> tf32 (one launch)
    wconv_kernel<<<7*WSZ/256, 256>>>(Wq_sw, Wk_sw, Wq, Wk, Wv, Wg, Wo, wt_);
    // 3. q_sw = (LN(msa[n=0]) @ Wq_sw + bq_sw) * scale
    gemmP<true,false,false,false,false><<<dim3(2,3), 256, GP_SMEM>>>(
        mt_, wt_ + 0*WSZ, bq_sw, nullptr, nullptr, nullptr, SCALE, qsw_, nullptr);
    // 4. sw_logits = (LN(msa) @ Wk_sw + bk_sw) . qsw
    gemmP<true,false,true,false,false><<<gproj, 256, GP_SMEM>>>(
        mt_, wt_ + 1*WSZ, bk_sw, qsw_, sw_, nullptr, 1.f, nullptr, nullptr);
    // 5. softmax over n -> seq_weight
    swsoftmax_kernel<<<Ll*Hh, 256>>>(sw_);
    // 6. q = (LN(msa) @ Wq) * seq_weight, tf32
    gemmP<false,false,false,true,true><<<gproj, 256, GP_SMEM>>>(
        mt_, wt_ + 2*WSZ, nullptr, nullptr, nullptr, sw_, 1.f, nullptr, qt_);
    // 7. k = (LN(msa) @ Wk) * scale, tf32
    gemmP<false,false,false,false,true><<<gproj, 256, GP_SMEM>>>(
        mt_, wt_ + 3*WSZ, nullptr, nullptr, nullptr, nullptr, SCALE, nullptr, kt_);
    // 8. v = LN(msa) @ Wv, tf32
    gemmP<false,false,false,false,true><<<gproj, 256, GP_SMEM>>>(
        mt_, wt_ + 4*WSZ, nullptr, nullptr, nullptr, nullptr, 1.f, nullptr, vt_);
    // 9. gate = sigmoid(LN(msa) @ Wg + bg), fp32
    gemmP<true,true,false,false,false><<<gproj, 256, GP_SMEM>>>(
        mt_, wt_ + 5*WSZ, bg, nullptr, nullptr, nullptr, 1.f, gg_, nullptr);
    // 10. pair bias
    pairbias_kernel<<<LLp, 128>>>(pair, ln_pair_g, ln_pair_b, Wb, bi_);
    // 11. logits (+bias)
    logitsP<<<dim3(3,3,8), 256, LG_SMEM>>>(qt_, kt_, bi_, lg_);
    // 12. attn = softmax(logits), tf32 in place
    attnsoftmax_kernel<<<Hh*Ll, Ll>>>(lg_);
    // 13. out = (attn @ v) * gate, tf32
    outP<<<dim3((Nn*DHh)/128, 3, 8), 256, GP_SMEM>>>((uint32_t*)lg_, vt_, gg_, ot_);
    // 14. y = out @ Wo + bo
    gemmP<true,false,false,false,false><<<dim3(2, NL/128), 256, GP_SMEM>>>(
        ot_, wt_ + 6*WSZ, bo, nullptr, nullptr, nullptr, 1.f, out, nullptr);
}